// round 3
// baseline (speedup 1.0000x reference)
#include <cuda_runtime.h>
#include <cuda_bf16.h>

#define Tn 100
#define Bn 16
#define En 128
#define Hn 256
#define Ln 2048
#define H2n 512
#define G4n 1024

#define OFF_OUT  0
#define OFF_HF   (Tn*Bn*Hn)
#define OFF_CF   (OFF_HF + Bn*Hn)
#define OFF_ATTN (OFF_CF + Bn*Hn)
#define OFF_PG   (OFF_ATTN + Tn*Bn*Ln)

// ------------- scratch (static device globals; no runtime alloc) -------------
__device__ float g_x[Tn*Bn*En];       // x_t for all steps
__device__ float g_xw[Tn*Bn*G4n];     // x @ Wih.T + bih
__device__ float g_ef[Bn*Ln*Hn];      // enc_feat
__device__ float g_e[Bn*Ln];          // attention logits (current step)
__device__ float g_m[Bn*16];          // per-chunk max
__device__ float g_s[Bn*16];          // per-chunk sum(exp*mask)
__device__ float g_h[2][Bn*Hn];       // double-buffered h
__device__ float g_c[2][Bn*Hn];
__device__ float g_dec[Bn*Hn];        // dec_feat
__device__ float g_ctxp[Bn*16*H2n];   // ctx partials per l-chunk

// ------------- helpers -------------
__device__ __forceinline__ float warp_sum(float v) {
    #pragma unroll
    for (int o = 16; o > 0; o >>= 1) v += __shfl_xor_sync(0xffffffffu, v, o);
    return v;
}
__device__ __forceinline__ float warp_max(float v) {
    #pragma unroll
    for (int o = 16; o > 0; o >>= 1) v = fmaxf(v, __shfl_xor_sync(0xffffffffu, v, o));
    return v;
}
__device__ __forceinline__ float tanh_acc(float x) {
    float ax = fabsf(x);
    float e  = __expf(-2.0f * ax);
    float r  = __fdividef(1.0f - e, 1.0f + e);
    return copysignf(r, x);
}
__device__ __forceinline__ float sigmoidf_(float x) {
    return __fdividef(1.0f, 1.0f + __expf(-x));
}
__device__ __forceinline__ float4 ld4(const float* p) { return *(const float4*)p; }

// ------------- init h,c -------------
__global__ void k_init(const float* __restrict__ h0, const float* __restrict__ c0) {
    int i = blockIdx.x * blockDim.x + threadIdx.x;
    if (i < Bn*Hn) { g_h[0][i] = h0[i]; g_c[0][i] = c0[i]; }
}

// ------------- x and x@Wih.T for all (t,b) -------------
__global__ __launch_bounds__(256) void k_xfuse(const float* __restrict__ dec,
        const float* __restrict__ Wx, const float* __restrict__ bx,
        const float* __restrict__ Wih, const float* __restrict__ bih) {
    __shared__ float sin_[8][En];
    __shared__ float sx2[8][En];
    int r0 = blockIdx.x * 8;                    // rows = t*B+b
    int tid = threadIdx.x;
    for (int idx = tid; idx < 8*En; idx += 256)
        sin_[idx >> 7][idx & 127] = dec[(r0 + (idx >> 7))*En + (idx & 127)];
    __syncthreads();
    // phase 1: x = inp @ Wx[:, :E].T + bx
    {
        int j = tid & 127, rg = tid >> 7;       // rg = 0/1, rows rg*4..rg*4+3
        float acc[4] = {0.f, 0.f, 0.f, 0.f};
        #pragma unroll 8
        for (int k = 0; k < En; k += 4) {
            float4 w = ld4(&Wx[j*640 + k]);
            #pragma unroll
            for (int rr = 0; rr < 4; rr++) {
                const float* s = sin_[rg*4 + rr];
                acc[rr] += w.x*s[k] + w.y*s[k+1] + w.z*s[k+2] + w.w*s[k+3];
            }
        }
        float bb = bx[j];
        #pragma unroll
        for (int rr = 0; rr < 4; rr++) {
            float val = acc[rr] + bb;
            sx2[rg*4 + rr][j] = val;
            g_x[(r0 + rg*4 + rr)*En + j] = val;
        }
    }
    __syncthreads();
    // phase 2: xw = x @ Wih.T + bih
    for (int q = 0; q < 4; q++) {
        int g = q*256 + tid;
        float acc[8];
        #pragma unroll
        for (int r = 0; r < 8; r++) acc[r] = 0.f;
        #pragma unroll 4
        for (int k = 0; k < En; k += 4) {
            float4 w = ld4(&Wih[g*En + k]);
            #pragma unroll
            for (int r = 0; r < 8; r++)
                acc[r] += w.x*sx2[r][k] + w.y*sx2[r][k+1] + w.z*sx2[r][k+2] + w.w*sx2[r][k+3];
        }
        float bb = bih[g];
        #pragma unroll
        for (int r = 0; r < 8; r++) g_xw[(r0 + r)*G4n + g] = acc[r] + bb;
    }
}

// ------------- enc_feat = es @ Wh.T + bh -------------
__global__ __launch_bounds__(256) void k_encfeat(const float* __restrict__ es,
        const float* __restrict__ Wh, const float* __restrict__ bh) {
    __shared__ float sW[32*261];   // [k][h] padded
    __shared__ float sE[32*36];    // [k][l] padded (row 144B, 16B aligned)
    int b  = blockIdx.x >> 6;
    int l0 = (blockIdx.x & 63) * 32;
    int tid = threadIdx.x, lane = tid & 31, w = tid >> 5;
    float acc[32];
    #pragma unroll
    for (int i = 0; i < 32; i++) acc[i] = 0.f;

    for (int k0 = 0; k0 < H2n; k0 += 32) {
        #pragma unroll 4
        for (int hh = 0; hh < 32; hh++) {
            int h = w*32 + hh;
            sW[lane*261 + h] = Wh[h*H2n + k0 + lane];
        }
        for (int idx = tid; idx < 1024; idx += 256) {
            int l = idx >> 5, k = idx & 31;
            sE[k*36 + l] = es[(size_t)(b*Ln + l0 + l)*H2n + k0 + k];
        }
        __syncthreads();
        #pragma unroll 4
        for (int k = 0; k < 32; k++) {
            float wv = sW[k*261 + tid];
            #pragma unroll
            for (int i4 = 0; i4 < 8; i4++) {
                float4 e = ld4(&sE[k*36 + i4*4]);
                acc[i4*4+0] += e.x*wv; acc[i4*4+1] += e.y*wv;
                acc[i4*4+2] += e.z*wv; acc[i4*4+3] += e.w*wv;
            }
        }
        __syncthreads();
    }
    float bb = bh[tid];
    #pragma unroll
    for (int i = 0; i < 32; i++)
        g_ef[(size_t)(b*Ln + l0 + i)*Hn + tid] = acc[i] + bb;
}

// ------------- per step: epilogue(t-1) + LSTM(t). t in [0, Tn]. -------------
__global__ __launch_bounds__(256) void k_lstm(int t,
        const float* __restrict__ Whh, const float* __restrict__ bhh,
        const float* __restrict__ Wout, const float* __restrict__ bout,
        const float* __restrict__ Wpg, const float* __restrict__ bpg,
        float* __restrict__ out) {
    __shared__ float sh[Hn], sc[Hn], sctx[H2n], sg[Hn];
    int b = blockIdx.x >> 2, jq = blockIdx.x & 3;
    int tid = threadIdx.x, lane = tid & 31, w = tid >> 5;
    int pin = t & 1;
    sh[tid] = g_h[pin][b*Hn + tid];
    sc[tid] = g_c[pin][b*Hn + tid];
    if (t > 0) {
        for (int i = tid; i < H2n; i += 256) {
            float s = 0.f;
            #pragma unroll
            for (int p = 0; p < 16; p++) s += g_ctxp[(b*16 + p)*H2n + i];
            sctx[i] = s;
        }
    }
    __syncthreads();

    if (t > 0) {
        // outputs[t-1] = [h, ctx] @ Wout.T + bout   (this block: h in [jq*64, jq*64+64))
        for (int i = 0; i < 8; i++) {
            int h = jq*64 + w*8 + i;
            float acc = 0.f;
            #pragma unroll
            for (int q = 0; q < 6; q++) {
                int k = q*128 + lane*4;
                float4 wv = ld4(&Wout[h*768 + k]);
                float4 sv = (k < 256) ? ld4(&sh[k]) : ld4(&sctx[k - 256]);
                acc += wv.x*sv.x + wv.y*sv.y + wv.z*sv.z + wv.w*sv.w;
            }
            acc = warp_sum(acc);
            if (lane == 0) out[OFF_OUT + ((t-1)*Bn + b)*Hn + h] = acc + bout[h];
        }
        // p_gen[t-1] over [ctx, h, c, x]
        if (jq == 0 && w == 0) {
            float acc = 0.f;
            for (int idx = lane; idx < 1152; idx += 32) {
                float val = (idx < 512)  ? sctx[idx]
                          : (idx < 768)  ? sh[idx - 512]
                          : (idx < 1024) ? sc[idx - 768]
                                         : g_x[((t-1)*Bn + b)*En + idx - 1024];
                acc += val * Wpg[idx];
            }
            acc = warp_sum(acc);
            if (lane == 0) out[OFF_PG + (t-1)*Bn + b] = sigmoidf_(acc + bpg[0]);
        }
    }

    if (t < Tn) {
        // gates for j in [jq*64, jq*64+64): 256 dots of length 256
        for (int gi = 0; gi < 32; gi++) {
            int gl = w*32 + gi;                 // 0..255
            int gt = gl >> 6, jl = gl & 63;
            int grow = gt*Hn + jq*64 + jl;
            float acc = 0.f;
            #pragma unroll
            for (int q = 0; q < 2; q++) {
                int k = q*128 + lane*4;
                float4 wv = ld4(&Whh[grow*Hn + k]);
                float4 sv = ld4(&sh[k]);
                acc += wv.x*sv.x + wv.y*sv.y + wv.z*sv.z + wv.w*sv.w;
            }
            acc = warp_sum(acc);
            if (lane == 0)
                sg[gl] = acc + g_xw[(t*Bn + b)*G4n + grow] + bhh[grow];
        }
        __syncthreads();
        if (tid < 64) {
            int j = jq*64 + tid;
            float gi_ = sg[tid], gf = sg[64 + tid], gg = sg[128 + tid], go = sg[192 + tid];
            float cn = sigmoidf_(gf)*sc[j] + sigmoidf_(gi_)*tanh_acc(gg);
            float hn = sigmoidf_(go)*tanh_acc(cn);
            g_c[pin ^ 1][b*Hn + j] = cn;
            g_h[pin ^ 1][b*Hn + j] = hn;
        }
    } else if (jq == 0) {
        out[OFF_HF + b*Hn + tid] = sh[tid];
        out[OFF_CF + b*Hn + tid] = sc[tid];
    }
}

// ------------- dec_feat = [h_new; c_new] @ Ws.T + bs -------------
__global__ __launch_bounds__(256) void k_dec(int t,
        const float* __restrict__ Ws, const float* __restrict__ bs) {
    __shared__ float ss[H2n];
    int b = blockIdx.x >> 2, hq = blockIdx.x & 3;
    int tid = threadIdx.x, lane = tid & 31, w = tid >> 5;
    int p = (t & 1) ^ 1;
    ss[tid]      = g_h[p][b*Hn + tid];
    ss[Hn + tid] = g_c[p][b*Hn + tid];
    __syncthreads();
    for (int i = 0; i < 8; i++) {
        int h = hq*64 + w*8 + i;
        float acc = 0.f;
        #pragma unroll
        for (int q = 0; q < 4; q++) {
            int k = q*128 + lane*4;
            float4 wv = ld4(&Ws[h*H2n + k]);
            float4 sv = ld4(&ss[k]);
            acc += wv.x*sv.x + wv.y*sv.y + wv.z*sv.z + wv.w*sv.w;
        }
        acc = warp_sum(acc);
        if (lane == 0) g_dec[b*Hn + h] = acc + bs[h];
    }
}

// ------------- scores + per-chunk softmax partials -------------
__global__ __launch_bounds__(256) void k_scores(int t,
        const float* __restrict__ v, const float* __restrict__ mask) {
    __shared__ float sD[Hn], sV[Hn], sE[128], red[8];
    int b = blockIdx.x >> 4, lc = blockIdx.x & 15;
    int l0 = lc * 128;
    int tid = threadIdx.x, lane = tid & 31, w = tid >> 5;
    sD[tid] = g_dec[b*Hn + tid];
    sV[tid] = v[tid];
    __syncthreads();
    for (int i = 0; i < 16; i++) {
        int l = l0 + w*16 + i;
        const float* ef = &g_ef[(size_t)(b*Ln + l)*Hn];
        float acc = 0.f;
        #pragma unroll
        for (int q = 0; q < 2; q++) {
            int k = q*128 + lane*4;
            float4 e4 = ld4(&ef[k]);
            acc += sV[k  ] * tanh_acc(e4.x + sD[k  ]);
            acc += sV[k+1] * tanh_acc(e4.y + sD[k+1]);
            acc += sV[k+2] * tanh_acc(e4.z + sD[k+2]);
            acc += sV[k+3] * tanh_acc(e4.w + sD[k+3]);
        }
        acc = warp_sum(acc);
        if (lane == 0) { g_e[b*Ln + l] = acc; sE[w*16 + i] = acc; }
    }
    __syncthreads();
    float x = (tid < 128) ? sE[tid] : -1e30f;
    float mx = warp_max(x);
    if (lane == 0) red[w] = mx;
    __syncthreads();
    float m = red[0];
    #pragma unroll
    for (int i = 1; i < 8; i++) m = fmaxf(m, red[i]);
    float ex = (tid < 128) ? __expf(sE[tid] - m) * mask[b*Ln + l0 + tid] : 0.f;
    __syncthreads();
    float sx = warp_sum(ex);
    if (lane == 0) red[w] = sx;
    __syncthreads();
    if (tid == 0) {
        float s = 0.f;
        #pragma unroll
        for (int i = 0; i < 8; i++) s += red[i];
        g_m[b*16 + lc] = m;
        g_s[b*16 + lc] = s;
    }
}

// ------------- attn + ctx partials -------------
__global__ __launch_bounds__(256) void k_ctx(int t,
        const float* __restrict__ es, const float* __restrict__ mask,
        float* __restrict__ out) {
    __shared__ float sA[128];
    int b = blockIdx.x >> 4, ch = blockIdx.x & 15;
    int l0 = ch * 128;
    int tid = threadIdx.x;
    float M = -1e30f;
    #pragma unroll
    for (int c = 0; c < 16; c++) M = fmaxf(M, g_m[b*16 + c]);
    float S = 0.f;
    #pragma unroll
    for (int c = 0; c < 16; c++) S += g_s[b*16 + c] * __expf(g_m[b*16 + c] - M);
    float invS = __fdividef(1.f, S);
    if (tid < 128) {
        int l = l0 + tid;
        float a = __expf(g_e[b*Ln + l] - M) * mask[b*Ln + l] * invS;
        out[OFF_ATTN + (size_t)(t*Bn + b)*Ln + l] = a;
        sA[tid] = a;
    }
    __syncthreads();
    float acc0 = 0.f, acc1 = 0.f;
    #pragma unroll 4
    for (int l = 0; l < 128; l++) {
        float a = sA[l];
        const float* row = &es[(size_t)(b*Ln + l0 + l)*H2n];
        acc0 += a * row[tid];
        acc1 += a * row[tid + 256];
    }
    g_ctxp[(b*16 + ch)*H2n + tid]       = acc0;
    g_ctxp[(b*16 + ch)*H2n + tid + 256] = acc1;
}

// ------------- launcher -------------
extern "C" void kernel_launch(void* const* d_in, const int* in_sizes, int n_in,
                              void* d_out, int out_size) {
    const float* dec  = (const float*)d_in[0];
    const float* h0   = (const float*)d_in[1];
    const float* c0   = (const float*)d_in[2];
    const float* es   = (const float*)d_in[3];
    const float* mask = (const float*)d_in[4];
    const float* Wh   = (const float*)d_in[5];
    const float* bh   = (const float*)d_in[6];
    const float* Ws   = (const float*)d_in[7];
    const float* bs   = (const float*)d_in[8];
    const float* v    = (const float*)d_in[9];
    const float* Wx   = (const float*)d_in[10];
    const float* bx   = (const float*)d_in[11];
    const float* Wih  = (const float*)d_in[12];
    const float* bih  = (const float*)d_in[13];
    const float* Whh  = (const float*)d_in[14];
    const float* bhh  = (const float*)d_in[15];
    const float* Wpg  = (const float*)d_in[16];
    const float* bpg  = (const float*)d_in[17];
    const float* Wout = (const float*)d_in[18];
    const float* bout = (const float*)d_in[19];
    float* out = (float*)d_out;

    k_init<<<16, 256>>>(h0, c0);
    k_xfuse<<<200, 256>>>(dec, Wx, bx, Wih, bih);
    k_encfeat<<<1024, 256>>>(es, Wh, bh);
    for (int t = 0; t < Tn; t++) {
        k_lstm<<<64, 256>>>(t, Whh, bhh, Wout, bout, Wpg, bpg, out);
        k_dec<<<64, 256>>>(t, Ws, bs);
        k_scores<<<256, 256>>>(t, v, mask);
        k_ctx<<<256, 256>>>(t, es, mask, out);
    }
    k_lstm<<<64, 256>>>(Tn, Whh, bhh, Wout, bout, Wpg, bpg, out);
}